// round 3
// baseline (speedup 1.0000x reference)
#include <cuda_runtime.h>
#include <cuda_bf16.h>
#include <cstdint>

#define N_NODES 100000
#define MAX_EDGES 1600000
#define DIM 128

// -------- scratch (device globals only; no allocation allowed) ----------
__device__ float g_xlin[(size_t)N_NODES * DIM];  // x @ W^T
__device__ int   g_src [MAX_EDGES];
__device__ int   g_dst [MAX_EDGES];
__device__ int   g_cnt [N_NODES];                // incoming edge count (no self loop)
__device__ int   g_off [N_NODES + 1];            // CSR row offsets
__device__ int   g_cur [N_NODES];                // fill cursors
__device__ float g_dinv[N_NODES];                // rsqrt(cnt+1)
__device__ int   g_csr [MAX_EDGES];              // src node per CSR slot
__device__ int   g_is64;                         // edge_index layout flag

// ---------------- detect int64 vs int32 layout + zero counts -------------
// int64 little-endian values in [0, 2^31): every odd 32-bit word == 0.
__global__ void detect_zero_kernel(const int* __restrict__ eiw) {
    int i = blockIdx.x * blockDim.x + threadIdx.x;
    if (i < N_NODES) g_cnt[i] = 0;
    if (blockIdx.x == 0 && threadIdx.x == 0) {
        int is64 = 1;
        for (int k = 0; k < 128; k++)
            if (eiw[2 * k + 1] != 0) { is64 = 0; break; }
        g_is64 = is64;
    }
}

// ---------------- convert edge index to int32, clamped --------------------
__global__ void convert_kernel(const int* __restrict__ eiw, int E) {
    int e = blockIdx.x * blockDim.x + threadIdx.x;
    if (e >= E) return;
    int s, d;
    if (g_is64) {
        s = eiw[2 * e];            // low word of int64 src
        d = eiw[2 * (E + e)];      // low word of int64 dst
    } else {
        s = eiw[e];
        d = eiw[E + e];
    }
    // clamp: never allow a wild index to escape this kernel
    s = min(max(s, 0), N_NODES - 1);
    d = min(max(d, 0), N_NODES - 1);
    g_src[e] = s;
    g_dst[e] = d;
    atomicAdd(&g_cnt[d], 1);
}

// ---------------- single-block scan: offsets, cursors, dinv ---------------
#define SCAN_T 1024
#define SCAN_CHUNK ((N_NODES + SCAN_T - 1) / SCAN_T)
__global__ __launch_bounds__(SCAN_T) void scan_kernel(int E) {
    __shared__ int part[SCAN_T];
    int t = threadIdx.x;
    int start = t * SCAN_CHUNK;
    int end = start + SCAN_CHUNK;
    if (start > N_NODES) start = N_NODES;
    if (end > N_NODES) end = N_NODES;

    int sum = 0;
    for (int i = start; i < end; i++) sum += g_cnt[i];
    part[t] = sum;
    __syncthreads();

    for (int o = 1; o < SCAN_T; o <<= 1) {
        int v = 0;
        if (t >= o) v = part[t - o];
        __syncthreads();
        if (t >= o) part[t] += v;
        __syncthreads();
    }

    int run = (t == 0) ? 0 : part[t - 1];  // exclusive prefix
    for (int i = start; i < end; i++) {
        int c = g_cnt[i];
        g_off[i] = run;
        g_cur[i] = run;
        g_dinv[i] = rsqrtf((float)(c + 1));
        run += c;
    }
    if (t == SCAN_T - 1) g_off[N_NODES] = E;
}

// ---------------- fill CSR with src indices -------------------------------
__global__ void fill_kernel(int E) {
    int e = blockIdx.x * blockDim.x + threadIdx.x;
    if (e < E) {
        int pos = atomicAdd(&g_cur[g_dst[e]], 1);
        g_csr[pos] = g_src[e];
    }
}

// ---------------- GEMM: xlin = x @ W^T  (N x 128) -------------------------
#define GEMM_BM 128
#define XS_STRIDE (DIM + 1)
#define GEMM_SMEM_BYTES ((GEMM_BM * XS_STRIDE + DIM * DIM) * (int)sizeof(float))

__global__ __launch_bounds__(256) void gemm_kernel(const float* __restrict__ x,
                                                   const float* __restrict__ W,
                                                   int nrows) {
    extern __shared__ float smem[];
    float* xs = smem;                         // [128][129] padded
    float* wt = smem + GEMM_BM * XS_STRIDE;   // [k][o] = W[o][k]

    int t = threadIdx.x;
    int row0 = blockIdx.x * GEMM_BM;

    for (int i = t; i < DIM * DIM; i += 256) {
        int k = i >> 7;
        int o = i & 127;
        wt[k * DIM + o] = W[o * DIM + k];
    }
    for (int i = t; i < GEMM_BM * DIM; i += 256) {
        int r = i >> 7;
        int k = i & 127;
        int gr = row0 + r;
        xs[r * XS_STRIDE + k] = (gr < nrows) ? x[(size_t)gr * DIM + k] : 0.0f;
    }
    __syncthreads();

    int cg = (t & 15) * 8;
    int rg = (t >> 4) * 8;

    float acc[8][8];
#pragma unroll
    for (int i = 0; i < 8; i++)
#pragma unroll
        for (int j = 0; j < 8; j++) acc[i][j] = 0.0f;

#pragma unroll 4
    for (int k = 0; k < DIM; k++) {
        float a[8];
#pragma unroll
        for (int i = 0; i < 8; i++)
            a[i] = xs[(rg + i) * XS_STRIDE + k];
        float4 b0 = *(const float4*)&wt[k * DIM + cg];
        float4 b1 = *(const float4*)&wt[k * DIM + cg + 4];
        float bv[8] = {b0.x, b0.y, b0.z, b0.w, b1.x, b1.y, b1.z, b1.w};
#pragma unroll
        for (int i = 0; i < 8; i++)
#pragma unroll
            for (int j = 0; j < 8; j++)
                acc[i][j] = fmaf(a[i], bv[j], acc[i][j]);
    }

#pragma unroll
    for (int i = 0; i < 8; i++) {
        int gr = row0 + rg + i;
        if (gr < nrows) {
            float4* o = (float4*)&g_xlin[(size_t)gr * DIM + cg];
            o[0] = make_float4(acc[i][0], acc[i][1], acc[i][2], acc[i][3]);
            o[1] = make_float4(acc[i][4], acc[i][5], acc[i][6], acc[i][7]);
        }
    }
}

// ---------------- gather + finalize: one warp per node --------------------
// out[n] = dinv[n] * sum_{s in in(n)} dinv[s]*xlin[s]  + dinv[n]^2*xlin[n] + b
__global__ __launch_bounds__(256) void gather_kernel(const float* __restrict__ b,
                                                     float* __restrict__ out) {
    int warp = (blockIdx.x * blockDim.x + threadIdx.x) >> 5;
    if (warp >= N_NODES) return;
    int lane = threadIdx.x & 31;

    const float4* xlin4 = (const float4*)g_xlin;

    int base = g_off[warp];
    int cnt = g_off[warp + 1] - base;

    float4 acc = make_float4(0.f, 0.f, 0.f, 0.f);

    int k = 0;
    for (; k + 4 <= cnt; k += 4) {
        int s0 = __ldg(&g_csr[base + k + 0]);
        int s1 = __ldg(&g_csr[base + k + 1]);
        int s2 = __ldg(&g_csr[base + k + 2]);
        int s3 = __ldg(&g_csr[base + k + 3]);
        float n0 = __ldg(&g_dinv[s0]);
        float n1 = __ldg(&g_dinv[s1]);
        float n2 = __ldg(&g_dinv[s2]);
        float n3 = __ldg(&g_dinv[s3]);
        float4 v0 = __ldg(&xlin4[(size_t)s0 * 32 + lane]);
        float4 v1 = __ldg(&xlin4[(size_t)s1 * 32 + lane]);
        float4 v2 = __ldg(&xlin4[(size_t)s2 * 32 + lane]);
        float4 v3 = __ldg(&xlin4[(size_t)s3 * 32 + lane]);
        acc.x += n0 * v0.x + n1 * v1.x + n2 * v2.x + n3 * v3.x;
        acc.y += n0 * v0.y + n1 * v1.y + n2 * v2.y + n3 * v3.y;
        acc.z += n0 * v0.z + n1 * v1.z + n2 * v2.z + n3 * v3.z;
        acc.w += n0 * v0.w + n1 * v1.w + n2 * v2.w + n3 * v3.w;
    }
    for (; k < cnt; k++) {
        int s = __ldg(&g_csr[base + k]);
        float ns = __ldg(&g_dinv[s]);
        float4 v = __ldg(&xlin4[(size_t)s * 32 + lane]);
        acc.x += ns * v.x;
        acc.y += ns * v.y;
        acc.z += ns * v.z;
        acc.w += ns * v.w;
    }

    float di = g_dinv[warp];
    float di2 = di * di;
    float4 xl = xlin4[(size_t)warp * 32 + lane];
    float4 bb = ((const float4*)b)[lane];

    float4 r;
    r.x = di * acc.x + di2 * xl.x + bb.x;
    r.y = di * acc.y + di2 * xl.y + bb.y;
    r.z = di * acc.z + di2 * xl.z + bb.z;
    r.w = di * acc.w + di2 * xl.w + bb.w;
    ((float4*)out)[(size_t)warp * 32 + lane] = r;
}

// -------------------------------------------------------------------------
extern "C" void kernel_launch(void* const* d_in, const int* in_sizes, int n_in,
                              void* d_out, int out_size) {
    const float* x   = (const float*)d_in[0];
    const int*   eiw = (const int*)d_in[1];   // raw 32-bit view; layout detected on device
    const float* W   = (const float*)d_in[2];
    const float* b   = (const float*)d_in[3];
    float*       out = (float*)d_out;

    int E = in_sizes[1] / 2;   // element count is 2*E for both int32 and int64 layouts

    cudaFuncSetAttribute(gemm_kernel,
                         cudaFuncAttributeMaxDynamicSharedMemorySize,
                         GEMM_SMEM_BYTES);

    detect_zero_kernel<<<(N_NODES + 255) / 256, 256>>>(eiw);
    convert_kernel<<<(E + 255) / 256, 256>>>(eiw, E);
    scan_kernel<<<1, SCAN_T>>>(E);
    fill_kernel<<<(E + 255) / 256, 256>>>(E);
    gemm_kernel<<<(N_NODES + GEMM_BM - 1) / GEMM_BM, 256, GEMM_SMEM_BYTES>>>(x, W, N_NODES);

    int gather_blocks = (N_NODES * 32 + 255) / 256;
    gather_kernel<<<gather_blocks, 256>>>(b, out);
}

// round 4
// speedup vs baseline: 1.7707x; 1.7707x over previous
#include <cuda_runtime.h>
#include <cuda_bf16.h>
#include <cstdint>

#define N_NODES 100000
#define MAX_EDGES 1600000
#define DIM 128

// -------- scratch (device globals only; no allocation allowed) ----------
__device__ float g_xlin[(size_t)N_NODES * DIM];  // y = dinv * (x @ W^T)  (pre-scaled)
__device__ int   g_cnt [N_NODES];                // incoming edge count (no self loop)
__device__ int   g_off [N_NODES + 1];            // CSR row offsets
__device__ int   g_cur [N_NODES];                // fill cursors
__device__ float g_dinv[N_NODES];                // rsqrt(cnt+1)
__device__ int   g_csr [MAX_EDGES];              // src node per CSR slot
__device__ int   g_bsum[128];                    // per-block scan sums
__device__ int   g_boff[128];                    // exclusive block offsets
__device__ int   g_is64;                         // edge_index layout flag

#define SCAN_B 1024
#define N_SCAN_BLOCKS ((N_NODES + SCAN_B - 1) / SCAN_B)   // 98

// ---------------- detect int64 vs int32 layout + zero counts -------------
__global__ void detect_zero_kernel(const int* __restrict__ eiw) {
    int i = blockIdx.x * blockDim.x + threadIdx.x;
    if (i < N_NODES) g_cnt[i] = 0;
    if (blockIdx.x == 0 && threadIdx.x == 0) {
        int is64 = 1;
        for (int k = 0; k < 128; k++)
            if (eiw[2 * k + 1] != 0) { is64 = 0; break; }
        g_is64 = is64;
    }
}

// ---------------- count incoming edges per dst (reads ei directly) -------
__global__ void cnt_kernel(const int* __restrict__ eiw, int E) {
    int e = blockIdx.x * blockDim.x + threadIdx.x;
    if (e >= E) return;
    int d = g_is64 ? eiw[2 * (E + e)] : eiw[E + e];
    d = min(max(d, 0), N_NODES - 1);
    atomicAdd(&g_cnt[d], 1);
}

// ---------------- scan phase 1: per-block inclusive scan ------------------
__global__ __launch_bounds__(SCAN_B) void scan1_kernel() {
    __shared__ int sh[SCAN_B];
    int t = threadIdx.x;
    int i = blockIdx.x * SCAN_B + t;
    int c = (i < N_NODES) ? g_cnt[i] : 0;
    sh[t] = c;
    __syncthreads();
#pragma unroll
    for (int o = 1; o < SCAN_B; o <<= 1) {
        int v = (t >= o) ? sh[t - o] : 0;
        __syncthreads();
        sh[t] += v;
        __syncthreads();
    }
    if (i < N_NODES) {
        g_off[i] = sh[t] - c;                  // local exclusive prefix
        g_dinv[i] = rsqrtf((float)(c + 1));
    }
    if (t == SCAN_B - 1) g_bsum[blockIdx.x] = sh[t];
}

// ---------------- scan phase 2: scan the 98 block sums --------------------
__global__ void scan2_kernel(int nb) {
    __shared__ int sh[128];
    int t = threadIdx.x;
    int own = (t < nb) ? g_bsum[t] : 0;
    sh[t] = own;
    __syncthreads();
#pragma unroll
    for (int o = 1; o < 128; o <<= 1) {
        int v = (t >= o) ? sh[t - o] : 0;
        __syncthreads();
        sh[t] += v;
        __syncthreads();
    }
    if (t < nb) g_boff[t] = sh[t] - own;       // exclusive
}

// ---------------- scan phase 3: add block offsets, init cursors -----------
__global__ void scan3_kernel(int E) {
    int i = blockIdx.x * blockDim.x + threadIdx.x;
    if (i < N_NODES) {
        int o = g_off[i] + g_boff[i >> 10];
        g_off[i] = o;
        g_cur[i] = o;
    }
    if (i == 0) g_off[N_NODES] = E;
}

// ---------------- fill CSR with src indices (reads ei directly) -----------
__global__ void fill_kernel(const int* __restrict__ eiw, int E) {
    int e = blockIdx.x * blockDim.x + threadIdx.x;
    if (e >= E) return;
    int s, d;
    if (g_is64) {
        s = eiw[2 * e];
        d = eiw[2 * (E + e)];
    } else {
        s = eiw[e];
        d = eiw[E + e];
    }
    s = min(max(s, 0), N_NODES - 1);
    d = min(max(d, 0), N_NODES - 1);
    int pos = atomicAdd(&g_cur[d], 1);
    g_csr[pos] = s;
}

// ---------------- GEMM: y = dinv .* (x @ W^T)  (N x 128) ------------------
#define GEMM_BM 128
#define XS_STRIDE (DIM + 1)
#define GEMM_SMEM_BYTES ((GEMM_BM * XS_STRIDE + DIM * DIM) * (int)sizeof(float))

__global__ __launch_bounds__(256) void gemm_kernel(const float* __restrict__ x,
                                                   const float* __restrict__ W,
                                                   int nrows) {
    extern __shared__ float smem[];
    float* xs = smem;                         // [128][129] padded
    float* wt = smem + GEMM_BM * XS_STRIDE;   // [k][o] = W[o][k]

    int t = threadIdx.x;
    int row0 = blockIdx.x * GEMM_BM;

    for (int i = t; i < DIM * DIM; i += 256) {
        int k = i >> 7;
        int o = i & 127;
        wt[k * DIM + o] = W[o * DIM + k];
    }
    for (int i = t; i < GEMM_BM * DIM; i += 256) {
        int r = i >> 7;
        int k = i & 127;
        int gr = row0 + r;
        xs[r * XS_STRIDE + k] = (gr < nrows) ? x[(size_t)gr * DIM + k] : 0.0f;
    }
    __syncthreads();

    int cg = (t & 15) * 8;
    int rg = (t >> 4) * 8;

    float acc[8][8];
#pragma unroll
    for (int i = 0; i < 8; i++)
#pragma unroll
        for (int j = 0; j < 8; j++) acc[i][j] = 0.0f;

#pragma unroll 4
    for (int k = 0; k < DIM; k++) {
        float a[8];
#pragma unroll
        for (int i = 0; i < 8; i++)
            a[i] = xs[(rg + i) * XS_STRIDE + k];
        float4 b0 = *(const float4*)&wt[k * DIM + cg];
        float4 b1 = *(const float4*)&wt[k * DIM + cg + 4];
        float bv[8] = {b0.x, b0.y, b0.z, b0.w, b1.x, b1.y, b1.z, b1.w};
#pragma unroll
        for (int i = 0; i < 8; i++)
#pragma unroll
            for (int j = 0; j < 8; j++)
                acc[i][j] = fmaf(a[i], bv[j], acc[i][j]);
    }

#pragma unroll
    for (int i = 0; i < 8; i++) {
        int gr = row0 + rg + i;
        if (gr < nrows) {
            float sc = g_dinv[gr];            // pre-scale epilogue
            float4* o = (float4*)&g_xlin[(size_t)gr * DIM + cg];
            o[0] = make_float4(sc * acc[i][0], sc * acc[i][1], sc * acc[i][2], sc * acc[i][3]);
            o[1] = make_float4(sc * acc[i][4], sc * acc[i][5], sc * acc[i][6], sc * acc[i][7]);
        }
    }
}

// ---------------- gather + finalize: one warp per node --------------------
// out[n] = dinv[n] * ( sum_{s in in(n)} y[s] + y[n] ) + b,  y pre-scaled
__global__ __launch_bounds__(256) void gather_kernel(const float* __restrict__ b,
                                                     float* __restrict__ out) {
    int warp = (blockIdx.x * blockDim.x + threadIdx.x) >> 5;
    if (warp >= N_NODES) return;
    int lane = threadIdx.x & 31;

    const float4* y4 = (const float4*)g_xlin;

    int base = g_off[warp];
    int cnt = g_off[warp + 1] - base;

    float4 acc = make_float4(0.f, 0.f, 0.f, 0.f);

    int k = 0;
    for (; k + 8 <= cnt; k += 8) {
        int s[8];
#pragma unroll
        for (int j = 0; j < 8; j++) s[j] = __ldg(&g_csr[base + k + j]);
        float4 v[8];
#pragma unroll
        for (int j = 0; j < 8; j++) v[j] = __ldg(&y4[(size_t)s[j] * 32 + lane]);
#pragma unroll
        for (int j = 0; j < 8; j++) {
            acc.x += v[j].x;
            acc.y += v[j].y;
            acc.z += v[j].z;
            acc.w += v[j].w;
        }
    }
    for (; k < cnt; k++) {
        int s = __ldg(&g_csr[base + k]);
        float4 v = __ldg(&y4[(size_t)s * 32 + lane]);
        acc.x += v.x;
        acc.y += v.y;
        acc.z += v.z;
        acc.w += v.w;
    }

    // self loop (y already carries dinv[n])
    float4 yl = y4[(size_t)warp * 32 + lane];
    acc.x += yl.x;
    acc.y += yl.y;
    acc.z += yl.z;
    acc.w += yl.w;

    float di = g_dinv[warp];
    float4 bb = ((const float4*)b)[lane];

    float4 r;
    r.x = di * acc.x + bb.x;
    r.y = di * acc.y + bb.y;
    r.z = di * acc.z + bb.z;
    r.w = di * acc.w + bb.w;
    ((float4*)out)[(size_t)warp * 32 + lane] = r;
}

// -------------------------------------------------------------------------
extern "C" void kernel_launch(void* const* d_in, const int* in_sizes, int n_in,
                              void* d_out, int out_size) {
    const float* x   = (const float*)d_in[0];
    const int*   eiw = (const int*)d_in[1];   // raw 32-bit view; layout detected on device
    const float* W   = (const float*)d_in[2];
    const float* b   = (const float*)d_in[3];
    float*       out = (float*)d_out;

    int E = in_sizes[1] / 2;

    cudaFuncSetAttribute(gemm_kernel,
                         cudaFuncAttributeMaxDynamicSharedMemorySize,
                         GEMM_SMEM_BYTES);

    detect_zero_kernel<<<(N_NODES + 255) / 256, 256>>>(eiw);
    cnt_kernel<<<(E + 255) / 256, 256>>>(eiw, E);
    scan1_kernel<<<N_SCAN_BLOCKS, SCAN_B>>>();
    scan2_kernel<<<1, 128>>>(N_SCAN_BLOCKS);
    scan3_kernel<<<(N_NODES + 255) / 256, 256>>>(E);
    gemm_kernel<<<(N_NODES + GEMM_BM - 1) / GEMM_BM, 256, GEMM_SMEM_BYTES>>>(x, W, N_NODES);
    fill_kernel<<<(E + 255) / 256, 256>>>(eiw, E);

    int gather_blocks = (N_NODES * 32 + 255) / 256;
    gather_kernel<<<gather_blocks, 256>>>(b, out);
}

// round 6
// speedup vs baseline: 1.8921x; 1.0685x over previous
#include <cuda_runtime.h>
#include <cuda_bf16.h>
#include <cstdint>

#define N_NODES 100000
#define MAX_EDGES 1600000
#define DIM 128

// -------- scratch (device globals only; no allocation allowed) ----------
__device__ float g_xlin[(size_t)N_NODES * DIM];  // y = dinv * (x @ W^T)  (pre-scaled)
__device__ int   g_cnt [N_NODES];                // incoming edge count (no self loop)
__device__ int   g_off [N_NODES + 1];            // CSR row offsets
__device__ int   g_cur [N_NODES];                // fill cursors
__device__ float g_dinv[N_NODES];                // rsqrt(cnt+1)
__device__ int   g_csr [MAX_EDGES];              // src node per CSR slot
__device__ int   g_bsum[128];                    // per-block scan sums
__device__ int   g_boff[128];                    // exclusive block offsets
__device__ int   g_is64;                         // edge_index layout flag

#define SCAN_B 1024
#define N_SCAN_BLOCKS ((N_NODES + SCAN_B - 1) / SCAN_B)   // 98

// ---------------- detect int64 vs int32 layout + zero counts -------------
__global__ void detect_zero_kernel(const int* __restrict__ eiw) {
    int i = blockIdx.x * blockDim.x + threadIdx.x;
    if (i < N_NODES) g_cnt[i] = 0;
    if (blockIdx.x == 0 && threadIdx.x < 128) {
        // int64 little-endian values in [0,1e5): every odd 32-bit word == 0
        unsigned nz = __ballot_sync(0xFFFFFFFFu, eiw[2 * threadIdx.x + 1] != 0);
        if ((threadIdx.x & 31) == 0) {
            if (nz) atomicExch(&g_is64, 0);
            else if (threadIdx.x == 0) atomicCAS(&g_is64, g_is64, g_is64); // no-op touch
        }
        if (threadIdx.x == 0) g_is64 = 1;   // default; overwritten below if any nz
        __syncthreads();
        nz = __syncthreads_or(eiw[2 * threadIdx.x + 1] != 0);
        if (threadIdx.x == 0) g_is64 = nz ? 0 : 1;
    }
}

// ---------------- count incoming edges per dst (reads ei directly) -------
__global__ void cnt_kernel(const int* __restrict__ eiw, int E) {
    int e = blockIdx.x * blockDim.x + threadIdx.x;
    if (e >= E) return;
    int d = g_is64 ? eiw[2 * (E + e)] : eiw[E + e];
    d = min(max(d, 0), N_NODES - 1);
    atomicAdd(&g_cnt[d], 1);
}

// ---------------- dinv = rsqrt(cnt+1) (early, unblocks GEMM) --------------
__global__ void dinv_kernel() {
    int i = blockIdx.x * blockDim.x + threadIdx.x;
    if (i < N_NODES) g_dinv[i] = rsqrtf((float)(g_cnt[i] + 1));
}

// ---------------- scan phase 1: per-block inclusive scan ------------------
__global__ __launch_bounds__(SCAN_B) void scan1_kernel() {
    __shared__ int sh[SCAN_B];
    int t = threadIdx.x;
    int i = blockIdx.x * SCAN_B + t;
    int c = (i < N_NODES) ? g_cnt[i] : 0;
    sh[t] = c;
    __syncthreads();
#pragma unroll
    for (int o = 1; o < SCAN_B; o <<= 1) {
        int v = (t >= o) ? sh[t - o] : 0;
        __syncthreads();
        sh[t] += v;
        __syncthreads();
    }
    if (i < N_NODES) g_off[i] = sh[t] - c;     // local exclusive prefix
    if (t == SCAN_B - 1) g_bsum[blockIdx.x] = sh[t];
}

// ---------------- scan phase 2: scan the 98 block sums --------------------
__global__ void scan2_kernel(int nb) {
    __shared__ int sh[128];
    int t = threadIdx.x;
    int own = (t < nb) ? g_bsum[t] : 0;
    sh[t] = own;
    __syncthreads();
#pragma unroll
    for (int o = 1; o < 128; o <<= 1) {
        int v = (t >= o) ? sh[t - o] : 0;
        __syncthreads();
        sh[t] += v;
        __syncthreads();
    }
    if (t < nb) g_boff[t] = sh[t] - own;       // exclusive
}

// ---------------- scan phase 3: add block offsets, init cursors -----------
__global__ void scan3_kernel(int E) {
    int i = blockIdx.x * blockDim.x + threadIdx.x;
    if (i < N_NODES) {
        int o = g_off[i] + g_boff[i >> 10];
        g_off[i] = o;
        g_cur[i] = o;
    }
    if (i == 0) g_off[N_NODES] = E;
}

// ---------------- fill CSR with src indices (reads ei directly) -----------
__global__ void fill_kernel(const int* __restrict__ eiw, int E) {
    int e = blockIdx.x * blockDim.x + threadIdx.x;
    if (e >= E) return;
    int s, d;
    if (g_is64) {
        s = eiw[2 * e];
        d = eiw[2 * (E + e)];
    } else {
        s = eiw[e];
        d = eiw[E + e];
    }
    s = min(max(s, 0), N_NODES - 1);
    d = min(max(d, 0), N_NODES - 1);
    int pos = atomicAdd(&g_cur[d], 1);
    g_csr[pos] = s;
}

// ---------------- GEMM: y = dinv .* (x @ W^T)  (N x 128) ------------------
#define GEMM_BM 128
#define XS_STRIDE (DIM + 1)
#define GEMM_SMEM_BYTES ((GEMM_BM * XS_STRIDE + DIM * DIM) * (int)sizeof(float))

__global__ __launch_bounds__(256) void gemm_kernel(const float* __restrict__ x,
                                                   const float* __restrict__ W,
                                                   int nrows) {
    extern __shared__ float smem[];
    float* xs = smem;                         // [128][129] padded
    float* wt = smem + GEMM_BM * XS_STRIDE;   // [k][o] = W[o][k]

    int t = threadIdx.x;
    int row0 = blockIdx.x * GEMM_BM;

    for (int i = t; i < DIM * DIM; i += 256) {
        int k = i >> 7;
        int o = i & 127;
        wt[k * DIM + o] = W[o * DIM + k];
    }
    for (int i = t; i < GEMM_BM * DIM; i += 256) {
        int r = i >> 7;
        int k = i & 127;
        int gr = row0 + r;
        xs[r * XS_STRIDE + k] = (gr < nrows) ? x[(size_t)gr * DIM + k] : 0.0f;
    }
    __syncthreads();

    int cg = (t & 15) * 8;
    int rg = (t >> 4) * 8;

    float acc[8][8];
#pragma unroll
    for (int i = 0; i < 8; i++)
#pragma unroll
        for (int j = 0; j < 8; j++) acc[i][j] = 0.0f;

#pragma unroll 4
    for (int k = 0; k < DIM; k++) {
        float a[8];
#pragma unroll
        for (int i = 0; i < 8; i++)
            a[i] = xs[(rg + i) * XS_STRIDE + k];
        float4 b0 = *(const float4*)&wt[k * DIM + cg];
        float4 b1 = *(const float4*)&wt[k * DIM + cg + 4];
        float bv[8] = {b0.x, b0.y, b0.z, b0.w, b1.x, b1.y, b1.z, b1.w};
#pragma unroll
        for (int i = 0; i < 8; i++)
#pragma unroll
            for (int j = 0; j < 8; j++)
                acc[i][j] = fmaf(a[i], bv[j], acc[i][j]);
    }

#pragma unroll
    for (int i = 0; i < 8; i++) {
        int gr = row0 + rg + i;
        if (gr < nrows) {
            float sc = g_dinv[gr];            // pre-scale epilogue
            float4* o = (float4*)&g_xlin[(size_t)gr * DIM + cg];
            o[0] = make_float4(sc * acc[i][0], sc * acc[i][1], sc * acc[i][2], sc * acc[i][3]);
            o[1] = make_float4(sc * acc[i][4], sc * acc[i][5], sc * acc[i][6], sc * acc[i][7]);
        }
    }
}

// ---------------- gather + finalize: one warp per node --------------------
// out[n] = dinv[n] * ( sum_{s in in(n)} y[s] + y[n] ) + b,  y pre-scaled
__global__ __launch_bounds__(256) void gather_kernel(const float* __restrict__ b,
                                                     float* __restrict__ out) {
    int warp = (blockIdx.x * blockDim.x + threadIdx.x) >> 5;
    if (warp >= N_NODES) return;
    int lane = threadIdx.x & 31;

    const float4* y4 = (const float4*)g_xlin;

    int base = g_off[warp];
    int cnt = g_off[warp + 1] - base;

    float4 acc = make_float4(0.f, 0.f, 0.f, 0.f);

    int k = 0;
    for (; k + 8 <= cnt; k += 8) {
        int s[8];
#pragma unroll
        for (int j = 0; j < 8; j++) s[j] = __ldg(&g_csr[base + k + j]);
        float4 v[8];
#pragma unroll
        for (int j = 0; j < 8; j++) v[j] = __ldg(&y4[(size_t)s[j] * 32 + lane]);
#pragma unroll
        for (int j = 0; j < 8; j++) {
            acc.x += v[j].x;
            acc.y += v[j].y;
            acc.z += v[j].z;
            acc.w += v[j].w;
        }
    }
    for (; k < cnt; k++) {
        int s = __ldg(&g_csr[base + k]);
        float4 v = __ldg(&y4[(size_t)s * 32 + lane]);
        acc.x += v.x;
        acc.y += v.y;
        acc.z += v.z;
        acc.w += v.w;
    }

    // self loop (y already carries dinv[n])
    float4 yl = y4[(size_t)warp * 32 + lane];
    acc.x += yl.x;
    acc.y += yl.y;
    acc.z += yl.z;
    acc.w += yl.w;

    float di = g_dinv[warp];
    float4 bb = ((const float4*)b)[lane];

    float4 r;
    r.x = di * acc.x + bb.x;
    r.y = di * acc.y + bb.y;
    r.z = di * acc.z + bb.z;
    r.w = di * acc.w + bb.w;
    ((float4*)out)[(size_t)warp * 32 + lane] = r;
}

// -------------------------------------------------------------------------
extern "C" void kernel_launch(void* const* d_in, const int* in_sizes, int n_in,
                              void* d_out, int out_size) {
    const float* x   = (const float*)d_in[0];
    const int*   eiw = (const int*)d_in[1];   // raw 32-bit view; layout detected on device
    const float* W   = (const float*)d_in[2];
    const float* b   = (const float*)d_in[3];
    float*       out = (float*)d_out;

    int E = in_sizes[1] / 2;

    cudaFuncSetAttribute(gemm_kernel,
                         cudaFuncAttributeMaxDynamicSharedMemorySize,
                         GEMM_SMEM_BYTES);

    // fork/join resources (host-side only; no device memory)
    cudaStream_t s2;
    cudaStreamCreateWithFlags(&s2, cudaStreamNonBlocking);
    cudaEvent_t e1, e2;
    cudaEventCreateWithFlags(&e1, cudaEventDisableTiming);
    cudaEventCreateWithFlags(&e2, cudaEventDisableTiming);

    // serial prefix: detect -> cnt -> dinv
    detect_zero_kernel<<<(N_NODES + 255) / 256, 256>>>(eiw);
    cnt_kernel<<<(E + 255) / 256, 256>>>(eiw, E);
    dinv_kernel<<<(N_NODES + 255) / 256, 256>>>();

    // fork: GEMM (branch A) runs concurrently with CSR build (branch B)
    cudaEventRecord(e1, 0);
    cudaStreamWaitEvent(s2, e1, 0);
    gemm_kernel<<<(N_NODES + GEMM_BM - 1) / GEMM_BM, 256, GEMM_SMEM_BYTES, s2>>>(x, W, N_NODES);
    cudaEventRecord(e2, s2);

    scan1_kernel<<<N_SCAN_BLOCKS, SCAN_B>>>();
    scan2_kernel<<<1, 128>>>(N_SCAN_BLOCKS);
    scan3_kernel<<<(N_NODES + 255) / 256, 256>>>(E);
    fill_kernel<<<(E + 255) / 256, 256>>>(eiw, E);

    // join, then gather
    cudaStreamWaitEvent(0, e2, 0);
    int gather_blocks = (N_NODES * 32 + 255) / 256;
    gather_kernel<<<gather_blocks, 256>>>(b, out);

    cudaEventDestroy(e1);
    cudaEventDestroy(e2);
    cudaStreamDestroy(s2);
}